// round 4
// baseline (speedup 1.0000x reference)
#include <cuda_runtime.h>
#include <cuda_fp16.h>
#include <cstdint>

// Batch Conv1D as implicit-im2col GEMM using classic mma.sync (HMMA fp16/fp32).
// Round 4: x fp32->fp16 conversion fused into the GEMM A-path (pre-pass removed).
// x: [256 images][1024][256] f32; im2col row l = x[l*256 .. l*256+768) contiguous.
// W: [3,256,256] f32 -> fp16 g_wf16 [768][256] via tiny pre-pass.
// GEMM per CTA: M=128 rows x N=128 feats, K=768 in 24 chunks of 32.

namespace {

constexpr int LOUT = 1022;
constexpr int KTOT = 768;
constexpr int NIT  = KTOT / 32;          // 24 k-chunks
constexpr int NTHREADS = 256;

constexpr int A_STRIDE = 80;             // bytes per A smem row (32 fp16 + pad)
constexpr int B_STRIDE = 272;            // bytes per B smem row (128 fp16 + pad)
constexpr int A_BYTES  = 128 * A_STRIDE; // 10240
constexpr int B_BYTES  = 32 * B_STRIDE;  // 8704

__device__ __half g_wf16[KTOT * 256];

// ---------------- PTX helpers ----------------

__device__ __forceinline__ uint32_t smem_u32(const void* p) {
    return (uint32_t)__cvta_generic_to_shared(p);
}

__device__ __forceinline__ void cp16(uint32_t dst, const void* src) {
    asm volatile("cp.async.cg.shared.global [%0], [%1], 16;" :: "r"(dst), "l"(src));
}
__device__ __forceinline__ void cp_commit() {
    asm volatile("cp.async.commit_group;" ::: "memory");
}
__device__ __forceinline__ void cp_wait0() {
    asm volatile("cp.async.wait_group 0;" ::: "memory");
}

__device__ __forceinline__ void ldsm4(uint32_t (&r)[4], uint32_t addr) {
    asm volatile("ldmatrix.sync.aligned.m8n8.x4.shared.b16 {%0,%1,%2,%3}, [%4];"
                 : "=r"(r[0]), "=r"(r[1]), "=r"(r[2]), "=r"(r[3]) : "r"(addr));
}
__device__ __forceinline__ void ldsm4t(uint32_t (&r)[4], uint32_t addr) {
    asm volatile("ldmatrix.sync.aligned.m8n8.x4.trans.shared.b16 {%0,%1,%2,%3}, [%4];"
                 : "=r"(r[0]), "=r"(r[1]), "=r"(r[2]), "=r"(r[3]) : "r"(addr));
}

__device__ __forceinline__ void mma16816(float (&c)[4], const uint32_t (&a)[4],
                                         uint32_t b0, uint32_t b1) {
    asm volatile(
        "mma.sync.aligned.m16n8k16.row.col.f32.f16.f16.f32 "
        "{%0,%1,%2,%3}, {%4,%5,%6,%7}, {%8,%9}, {%0,%1,%2,%3};"
        : "+f"(c[0]), "+f"(c[1]), "+f"(c[2]), "+f"(c[3])
        : "r"(a[0]), "r"(a[1]), "r"(a[2]), "r"(a[3]), "r"(b0), "r"(b1));
}

__device__ __forceinline__ uint32_t pack_h2(float a, float b) {
    __half2 h = __floats2half2_rn(a, b);
    return *(uint32_t*)&h;
}

// ---------------- pre-pass: W fp32 -> fp16 ----------------

__global__ void wconv_kernel(const float* __restrict__ W) {
    int i = blockIdx.x * 256 + threadIdx.x;              // 768*256 threads
    g_wf16[i] = __float2half_rn(W[i]);
}

// ---------------- main GEMM kernel (fused x conversion) ----------------

__global__ __launch_bounds__(NTHREADS, 2)
void conv1d_hmma_kernel(const float* __restrict__ x,
                        const float* __restrict__ bias,
                        float* __restrict__ out)
{
    __shared__ __align__(128) uint8_t smA[2][A_BYTES];
    __shared__ __align__(128) uint8_t smB[2][B_BYTES];

    const int tid  = threadIdx.x;
    const int wid  = tid >> 5;
    const int lane = tid & 31;

    const int f0  = blockIdx.x * 128;       // feature tile
    const int l0  = blockIdx.y * 128;       // row tile
    const int img = blockIdx.z;

    const float* xb = x   + (size_t)img * (1024 * 256);
    float*       ob = out + (size_t)img * (LOUT * 256);

    // warp tile: 32 (m) x 64 (n); 4 warps along m, 2 along n
    const int wm = (wid >> 1) * 32;
    const int wn = (wid & 1) * 64;

    const uint32_t sA0 = smem_u32(&smA[0][0]);
    const uint32_t sA1 = smem_u32(&smA[1][0]);
    const uint32_t sB0 = smem_u32(&smB[0][0]);
    const uint32_t sB1 = smem_u32(&smB[1][0]);

    // ---- A staging: 128 rows x 32 fp32 per chunk; 16 fp32 per thread ----
    const int  a_row = tid >> 1;             // 0..127
    const int  a_sg  = tid & 1;              // half-row: 16 fp32
    const bool a_ok  = (l0 + a_row) < LOUT;  // last valid row reads exactly to x end
    const float* a_src = xb + (size_t)(l0 + a_row) * 256 + a_sg * 16;
    const uint32_t a_dst = a_row * A_STRIDE + a_sg * 32;   // 32 bytes = 16 fp16

    // ---- B staging via cp.async (fp16, pre-converted W) ----
    const int b_row = tid >> 3;              // 0..31
    const int b_cg  = tid & 7;
    const __half* b_src = g_wf16 + (size_t)b_row * 256 + f0 + b_cg * 16;
    const uint32_t b_dst = b_row * B_STRIDE + b_cg * 32;

    // ldmatrix lane base offsets
    const uint32_t a_lane = (uint32_t)(wm + (lane & 15)) * A_STRIDE + (lane >> 4) * 16;
    const uint32_t b_lane = (uint32_t)(lane & 15) * B_STRIDE
                          + (uint32_t)(wn + (lane >> 4) * 8) * 2;

    float acc[2][8][4];
    #pragma unroll
    for (int mt = 0; mt < 2; ++mt)
        #pragma unroll
        for (int nt = 0; nt < 8; ++nt)
            #pragma unroll
            for (int q = 0; q < 4; ++q)
                acc[mt][nt][q] = 0.f;

    float4 ar[4];

    // ---- prologue: stage chunk 0 ----
    if (a_ok) {
        #pragma unroll
        for (int q = 0; q < 4; ++q) ar[q] = *(const float4*)(a_src + q * 4);
    } else {
        #pragma unroll
        for (int q = 0; q < 4; ++q) ar[q] = make_float4(0.f, 0.f, 0.f, 0.f);
    }
    cp16(sB0 + b_dst,      b_src);
    cp16(sB0 + b_dst + 16, b_src + 8);
    cp_commit();
    {
        uint4 u0, u1;
        u0.x = pack_h2(ar[0].x, ar[0].y); u0.y = pack_h2(ar[0].z, ar[0].w);
        u0.z = pack_h2(ar[1].x, ar[1].y); u0.w = pack_h2(ar[1].z, ar[1].w);
        u1.x = pack_h2(ar[2].x, ar[2].y); u1.y = pack_h2(ar[2].z, ar[2].w);
        u1.z = pack_h2(ar[3].x, ar[3].y); u1.w = pack_h2(ar[3].z, ar[3].w);
        *(uint4*)(&smA[0][a_dst])      = u0;
        *(uint4*)(&smA[0][a_dst + 16]) = u1;
    }
    cp_wait0();
    __syncthreads();

    for (int t = 0; t < NIT; ++t) {
        const uint32_t sA = (t & 1) ? sA1 : sA0;
        const uint32_t sB = (t & 1) ? sB1 : sB0;
        const bool more = (t + 1) < NIT;

        // 1) start next A loads (fp32) — latency hidden under this chunk's MMAs
        if (more) {
            if (a_ok) {
                const float* p = a_src + (t + 1) * 32;
                #pragma unroll
                for (int q = 0; q < 4; ++q) ar[q] = *(const float4*)(p + q * 4);
            }
            // 2) start next B cp.async — flies during the MMA block
            const uint32_t nB = (t & 1) ? sB0 : sB1;
            const __half* bsrc = b_src + (size_t)(t + 1) * 32 * 256;
            cp16(nB + b_dst,      bsrc);
            cp16(nB + b_dst + 16, bsrc + 8);
            cp_commit();
        }

        // 3) compute on current buffers
        #pragma unroll
        for (int ks = 0; ks < 2; ++ks) {
            uint32_t af[2][4];
            ldsm4(af[0], sA + a_lane + ks * 32);
            ldsm4(af[1], sA + a_lane + 16 * A_STRIDE + ks * 32);
            uint32_t bf[4][4];
            #pragma unroll
            for (int n2 = 0; n2 < 4; ++n2)
                ldsm4t(bf[n2], sB + b_lane + ks * (16 * B_STRIDE) + n2 * 32);
            #pragma unroll
            for (int mt = 0; mt < 2; ++mt)
                #pragma unroll
                for (int n2 = 0; n2 < 4; ++n2) {
                    mma16816(acc[mt][2 * n2],     af[mt], bf[n2][0], bf[n2][1]);
                    mma16816(acc[mt][2 * n2 + 1], af[mt], bf[n2][2], bf[n2][3]);
                }
        }

        // 4) convert + store next A chunk; wait for next B; barrier
        if (more) {
            uint8_t* dA = (t & 1) ? &smA[0][0] : &smA[1][0];
            uint4 u0, u1;
            u0.x = pack_h2(ar[0].x, ar[0].y); u0.y = pack_h2(ar[0].z, ar[0].w);
            u0.z = pack_h2(ar[1].x, ar[1].y); u0.w = pack_h2(ar[1].z, ar[1].w);
            u1.x = pack_h2(ar[2].x, ar[2].y); u1.y = pack_h2(ar[2].z, ar[2].w);
            u1.z = pack_h2(ar[3].x, ar[3].y); u1.w = pack_h2(ar[3].z, ar[3].w);
            *(uint4*)(dA + a_dst)      = u0;
            *(uint4*)(dA + a_dst + 16) = u1;
            cp_wait0();
        }
        __syncthreads();
    }

    // ---- epilogue: bias + guarded store straight from registers ----
    const int g  = lane >> 2;
    const int tq = lane & 3;
    #pragma unroll
    for (int nt = 0; nt < 8; ++nt) {
        const int col = f0 + wn + nt * 8 + tq * 2;
        const float b0 = __ldg(bias + col);
        const float b1 = __ldg(bias + col + 1);
        #pragma unroll
        for (int mt = 0; mt < 2; ++mt) {
            const int r = l0 + wm + mt * 16 + g;
            if (r < LOUT) {
                float2 v = make_float2(acc[mt][nt][0] + b0, acc[mt][nt][1] + b1);
                *(float2*)(ob + (size_t)r * 256 + col) = v;
            }
            if (r + 8 < LOUT) {
                float2 v = make_float2(acc[mt][nt][2] + b0, acc[mt][nt][3] + b1);
                *(float2*)(ob + (size_t)(r + 8) * 256 + col) = v;
            }
        }
    }
}

}  // namespace

extern "C" void kernel_launch(void* const* d_in, const int* in_sizes, int n_in,
                              void* d_out, int out_size)
{
    const float* x  = (const float*)d_in[0];   // [8,32,1024,256]
    const float* w  = (const float*)d_in[1];   // [3,256,256]
    const float* b  = (const float*)d_in[2];   // [256]
    float* out      = (float*)d_out;           // [8,32,1022,256]

    wconv_kernel<<<KTOT, 256>>>(w);            // tiny: W fp32 -> fp16

    dim3 grid(2, 8, 256);                      // f-tiles, m-tiles, images
    conv1d_hmma_kernel<<<grid, NTHREADS>>>(x, b, out);
}

// round 5
// speedup vs baseline: 1.1354x; 1.1354x over previous
#include <cuda_runtime.h>
#include <cuda_fp16.h>
#include <cstdint>

// Batch Conv1D, implicit-im2col GEMM on mma.sync (HMMA fp16/fp32 accum).
// Round 5: L1-traffic reduction.
//   - 64x64 warp tiles (4 warps / 128x128 CTA): LDSM dup A x2, B x2.
//   - conv tap-reuse: K ordered as (8 channel-chunks x 3 taps); one x tile of
//     130 rows x 32 ch serves all 3 taps (ldmatrix row base shifts by tap).
//   - x pre-converted to fp16 (xconv pre-pass, DRAM-roofline ~56us).
//
// x: [256 imgs][1024][256] f32 -> g_xh fp16. W: [3,256,256] f32 -> g_wf16 [768][256].

namespace {

constexpr int LOUT = 1022;
constexpr int KTOT = 768;
constexpr int NTHREADS = 128;

constexpr int A_STRIDE = 80;              // 32 fp16 (64B) + 16B pad
constexpr int A_ROWS   = 130;             // 128 outputs + 2 taps
constexpr int A_BYTES  = A_ROWS * A_STRIDE;   // 10400
constexpr int B_STRIDE = 272;             // 128 fp16 (256B) + 16B pad
constexpr int B_BYTES  = 32 * B_STRIDE;   // 8704

constexpr size_t X_ELEMS = 256u * 1024u * 256u;

__device__ __half g_wf16[KTOT * 256];
__device__ __half g_xh[X_ELEMS];

// ---------------- PTX helpers ----------------

__device__ __forceinline__ uint32_t smem_u32(const void* p) {
    return (uint32_t)__cvta_generic_to_shared(p);
}
__device__ __forceinline__ void cp16(uint32_t dst, const void* src) {
    asm volatile("cp.async.cg.shared.global [%0], [%1], 16;" :: "r"(dst), "l"(src));
}
__device__ __forceinline__ void cp_commit() {
    asm volatile("cp.async.commit_group;" ::: "memory");
}
__device__ __forceinline__ void cp_wait0() {
    asm volatile("cp.async.wait_group 0;" ::: "memory");
}
__device__ __forceinline__ void ldsm4(uint32_t (&r)[4], uint32_t addr) {
    asm volatile("ldmatrix.sync.aligned.m8n8.x4.shared.b16 {%0,%1,%2,%3}, [%4];"
                 : "=r"(r[0]), "=r"(r[1]), "=r"(r[2]), "=r"(r[3]) : "r"(addr));
}
__device__ __forceinline__ void ldsm4t(uint32_t (&r)[4], uint32_t addr) {
    asm volatile("ldmatrix.sync.aligned.m8n8.x4.trans.shared.b16 {%0,%1,%2,%3}, [%4];"
                 : "=r"(r[0]), "=r"(r[1]), "=r"(r[2]), "=r"(r[3]) : "r"(addr));
}
__device__ __forceinline__ void mma16816(float (&c)[4], const uint32_t (&a)[4],
                                         uint32_t b0, uint32_t b1) {
    asm volatile(
        "mma.sync.aligned.m16n8k16.row.col.f32.f16.f16.f32 "
        "{%0,%1,%2,%3}, {%4,%5,%6,%7}, {%8,%9}, {%0,%1,%2,%3};"
        : "+f"(c[0]), "+f"(c[1]), "+f"(c[2]), "+f"(c[3])
        : "r"(a[0]), "r"(a[1]), "r"(a[2]), "r"(a[3]), "r"(b0), "r"(b1));
}

// ---------------- pre-passes ----------------

__global__ void xconv_kernel(const float* __restrict__ x) {
    size_t i = (size_t)blockIdx.x * 256 + threadIdx.x;   // one uint4 (8 fp16)/thread
    const float4 v0 = *(const float4*)(x + i * 8);
    const float4 v1 = *(const float4*)(x + i * 8 + 4);
    __half2 h0 = __floats2half2_rn(v0.x, v0.y);
    __half2 h1 = __floats2half2_rn(v0.z, v0.w);
    __half2 h2 = __floats2half2_rn(v1.x, v1.y);
    __half2 h3 = __floats2half2_rn(v1.z, v1.w);
    uint4 p;
    p.x = *(uint32_t*)&h0; p.y = *(uint32_t*)&h1;
    p.z = *(uint32_t*)&h2; p.w = *(uint32_t*)&h3;
    *(uint4*)(g_xh + i * 8) = p;
}

__global__ void wconv_kernel(const float* __restrict__ W) {
    int i = blockIdx.x * 256 + threadIdx.x;
    g_wf16[i] = __float2half_rn(W[i]);
}

// ---------------- main GEMM ----------------

__global__ __launch_bounds__(NTHREADS, 2)
void conv1d_hmma_kernel(const float* __restrict__ bias, float* __restrict__ out)
{
    __shared__ __align__(128) uint8_t smA[2][A_BYTES];
    __shared__ __align__(128) uint8_t smB[2][B_BYTES];

    const int tid  = threadIdx.x;
    const int wid  = tid >> 5;
    const int lane = tid & 31;

    const int f0  = blockIdx.x * 128;
    const int l0  = blockIdx.y * 128;
    const int img = blockIdx.z;

    const __half* xb = g_xh + (size_t)img * (1024 * 256);
    float*        ob = out  + (size_t)img * (LOUT * 256);

    // 2x2 warp grid, 64x64 warp tiles
    const int wm = (wid >> 1) * 64;
    const int wn = (wid & 1) * 64;

    const uint32_t sAb[2] = { smem_u32(&smA[0][0]), smem_u32(&smA[1][0]) };
    const uint32_t sBb[2] = { smem_u32(&smB[0][0]), smem_u32(&smB[1][0]) };

    // ldmatrix lane bases
    const uint32_t a_lane = (uint32_t)(wm + (lane & 15)) * A_STRIDE + (lane >> 4) * 16;
    const uint32_t b_lane = (uint32_t)(lane & 15) * B_STRIDE
                          + (uint32_t)(wn + (lane >> 4) * 8) * 2;

    // ---- staging helpers ----
    // A: rows 0..129 of x channels [c*32, c*32+32), fp16 (64B/row = 4 cp16)
    auto stageA = [&](int c, int buf) {
        {
            const int xr = l0 + tid;                     // rows 0..127
            const __half* s = xb + (size_t)(xr < 1024 ? xr : 1023) * 256 + c * 32;
            const uint32_t d = sAb[buf] + (uint32_t)tid * A_STRIDE;
            cp16(d,      s);
            cp16(d + 16, s + 8);
            cp16(d + 32, s + 16);
            cp16(d + 48, s + 24);
        }
        if (tid < 2) {                                   // rows 128,129
            const int r  = 128 + tid;
            const int xr = l0 + r;
            const __half* s = xb + (size_t)(xr < 1024 ? xr : 1023) * 256 + c * 32;
            const uint32_t d = sAb[buf] + (uint32_t)r * A_STRIDE;
            cp16(d,      s);
            cp16(d + 16, s + 8);
            cp16(d + 32, s + 16);
            cp16(d + 48, s + 24);
        }
    };
    // B: k-rows [tap*256 + c*32 .. +32) x 128 features (256B/row = 16 cp16)
    auto stageB = [&](int tap, int c, int buf) {
        const int kr = tap * 256 + c * 32 + (tid >> 2);
        const __half* s = g_wf16 + (size_t)kr * 256 + f0 + (tid & 3) * 32;
        const uint32_t d = sBb[buf] + (uint32_t)(tid >> 2) * B_STRIDE + (tid & 3) * 64;
        cp16(d,      s);
        cp16(d + 16, s + 8);
        cp16(d + 32, s + 16);
        cp16(d + 48, s + 24);
    };

    float acc[4][8][4];
    #pragma unroll
    for (int mt = 0; mt < 4; ++mt)
        #pragma unroll
        for (int nt = 0; nt < 8; ++nt)
            #pragma unroll
            for (int q = 0; q < 4; ++q)
                acc[mt][nt][q] = 0.f;

    // prologue: stage A(c=0), B(step 0)
    stageA(0, 0);
    stageB(0, 0, 0);
    cp_commit();
    cp_wait0();
    __syncthreads();

    for (int c = 0; c < 8; ++c) {
        #pragma unroll
        for (int tap = 0; tap < 3; ++tap) {
            const int s = c * 3 + tap;
            const bool more = (s + 1) < 24;

            // prefetch next buffers (overlaps the MMA block below)
            if (tap == 0 && c + 1 < 8) stageA(c + 1, (c + 1) & 1);
            if (more) {
                const int ntap = (tap == 2) ? 0 : tap + 1;
                const int nc   = (tap == 2) ? c + 1 : c;
                stageB(ntap, nc, (s + 1) & 1);
            }
            cp_commit();

            // MMA block: A row base shifted by tap (conv tap-reuse)
            const uint32_t sA = sAb[c & 1] + (uint32_t)tap * A_STRIDE;
            const uint32_t sB = sBb[s & 1];
            #pragma unroll
            for (int ks = 0; ks < 2; ++ks) {
                uint32_t af[4][4];
                #pragma unroll
                for (int mt = 0; mt < 4; ++mt)
                    ldsm4(af[mt], sA + a_lane + mt * (16 * A_STRIDE) + ks * 32);
                uint32_t bf[4][4];
                #pragma unroll
                for (int n2 = 0; n2 < 4; ++n2)
                    ldsm4t(bf[n2], sB + b_lane + ks * (16 * B_STRIDE) + n2 * 32);
                #pragma unroll
                for (int mt = 0; mt < 4; ++mt)
                    #pragma unroll
                    for (int n2 = 0; n2 < 4; ++n2) {
                        mma16816(acc[mt][2 * n2],     af[mt], bf[n2][0], bf[n2][1]);
                        mma16816(acc[mt][2 * n2 + 1], af[mt], bf[n2][2], bf[n2][3]);
                    }
            }

            if (more) cp_wait0();
            __syncthreads();
        }
    }

    // ---- epilogue: bias + guarded store from registers ----
    const int g  = lane >> 2;
    const int tq = lane & 3;
    #pragma unroll
    for (int nt = 0; nt < 8; ++nt) {
        const int col = f0 + wn + nt * 8 + tq * 2;
        const float b0 = __ldg(bias + col);
        const float b1 = __ldg(bias + col + 1);
        #pragma unroll
        for (int mt = 0; mt < 4; ++mt) {
            const int r = l0 + wm + mt * 16 + g;
            if (r < LOUT) {
                float2 v = make_float2(acc[mt][nt][0] + b0, acc[mt][nt][1] + b1);
                *(float2*)(ob + (size_t)r * 256 + col) = v;
            }
            if (r + 8 < LOUT) {
                float2 v = make_float2(acc[mt][nt][2] + b0, acc[mt][nt][3] + b1);
                *(float2*)(ob + (size_t)(r + 8) * 256 + col) = v;
            }
        }
    }
}

}  // namespace

extern "C" void kernel_launch(void* const* d_in, const int* in_sizes, int n_in,
                              void* d_out, int out_size)
{
    const float* x  = (const float*)d_in[0];   // [8,32,1024,256]
    const float* w  = (const float*)d_in[1];   // [3,256,256]
    const float* b  = (const float*)d_in[2];   // [256]
    float* out      = (float*)d_out;           // [8,32,1022,256]

    xconv_kernel<<<(int)(X_ELEMS / 8 / 256), 256>>>(x);  // x fp32 -> fp16
    wconv_kernel<<<KTOT, 256>>>(w);                      // W fp32 -> fp16

    dim3 grid(2, 8, 256);                      // f-tiles, m-tiles, images
    conv1d_hmma_kernel<<<grid, NTHREADS>>>(b, out);
}